// round 10
// baseline (speedup 1.0000x reference)
#include <cuda_runtime.h>
#include <cstdint>

#define Bq 8
#define Nq 1024
#define Cq 128
#define Hq 4
#define Fq 32
#define HF (Hq*Fq)
#define MAXN 128
#define RPB 16                   // rows per gemm block
#define COLH 64                  // cols per gemm block (half of HF)
#define GEMM_BLKS ((Bq*Nq/RPB)*2)   // 512 row-tiles x 2 col-halves = 1024
#define XPAD 20                  // 80B row stride: 16B-aligned float4 loads

__device__ float g_buf[Bq*Nq*HF];      // g[b][j][h][f]
__device__ float si_t[Nq*32];          // [i][h*8+b]
__device__ float sj_t[Nq*32];          // [j][h*8+b]
__device__ int   jlist_buf[Nq*MAXN];   // byte offsets j*512
__device__ int   nnz_buf[Nq];

__device__ __forceinline__ unsigned long long pack2(float lo, float hi) {
    unsigned long long r;
    asm("mov.b64 %0, {%1, %2};" : "=l"(r) : "f"(lo), "f"(hi));
    return r;
}
__device__ __forceinline__ void unpack2(float& lo, float& hi, unsigned long long v) {
    asm("mov.b64 {%0, %1}, %2;" : "=f"(lo), "=f"(hi) : "l"(v));
}
__device__ __forceinline__ void fma2(unsigned long long& d, unsigned long long a,
                                     unsigned long long b) {
    asm("fma.rn.f32x2 %0, %1, %2, %0;" : "+l"(d) : "l"(a), "l"(b));
}

// ---------------------------------------------------------------------------
// Fused prep, 256 threads/block:
//   blocks [0,GEMM_BLKS): GEMM tile 16 rows x 64 cols, W stripe cached in smem.
//   blocks [GEMM_BLKS, +Nq): CSR build, thread owns 4 adj columns.
__global__ void __launch_bounds__(256) gat_prep_kernel(
    const float* __restrict__ x, const float* __restrict__ W,
    const float* __restrict__ a, const int* __restrict__ adj)
{
    __shared__ __align__(16) float ws[Cq*COLH];    // W[:, colbase:colbase+64]
    __shared__ __align__(16) float xs[Cq][XPAD];   // transposed x: [k][row 0..15]
    __shared__ int wtot[8];
    const int t = threadIdx.x;

    if (blockIdx.x >= GEMM_BLKS) {
        // ---------------- CSR for row i ----------------
        const int i = blockIdx.x - GEMM_BLKS;
        const int w = t >> 5, lane = t & 31;
        int4 v = ((const int4*)(adj + i*Nq))[t];      // cols 4t..4t+3
        unsigned m4 = 0;
        m4 |= (v.x != 0) ? 1u : 0u;  m4 |= (v.y != 0) ? 2u : 0u;
        m4 |= (v.z != 0) ? 4u : 0u;  m4 |= (v.w != 0) ? 8u : 0u;
        int cnt = __popc(m4);

        int incl = cnt;
        #pragma unroll
        for (int o = 1; o < 32; o <<= 1) {
            int n = __shfl_up_sync(0xffffffffu, incl, o);
            if (lane >= o) incl += n;
        }
        if (lane == 31) wtot[w] = incl;
        __syncthreads();
        int add = 0;
        #pragma unroll
        for (int ww = 0; ww < 8; ww++) add += (ww < w) ? wtot[ww] : 0;
        int pos = add + incl - cnt;

        unsigned mm = m4;
        while (mm) {
            int bit = __ffs(mm) - 1;
            mm &= mm - 1u;
            if (pos < MAXN) jlist_buf[i*MAXN + pos] = (t*4 + bit) * (HF*4);
            pos++;
        }
        if (t == 255) nnz_buf[i] = min(add + incl, MAXN);
        return;
    }

    // ---------------- GEMM: 16 rows x 64 cols ----------------
    const int rowtile = blockIdx.x >> 1;
    const int colbase = (blockIdx.x & 1) << 6;     // 0 or 64
    const int row0 = rowtile * RPB;                // b*Nq + i0
    const int b    = row0 >> 10;
    const int i0   = row0 & (Nq - 1);

    // stage W stripe: 128 x 64 floats = 2048 float4, 8 per thread
    {
        float4* wsv = (float4*)ws;
        #pragma unroll
        for (int q = 0; q < 8; q++) {
            int idx = q*256 + t;                   // 0..2047
            int k = idx >> 4, c4 = idx & 15;
            wsv[idx] = *(const float4*)&W[k*HF + colbase + c4*4];
        }
    }
    // stage x tile transposed: thread (c2 = t&127, rhalf = t>>7) loads 8 rows
    {
        const int c2 = t & 127, rhalf = t >> 7;
        #pragma unroll
        for (int r = 0; r < 8; r++)
            xs[c2][rhalf*8 + r] = x[(row0 + rhalf*8 + r)*Cq + c2];
    }
    __syncthreads();

    const int col = t & 63;        // 0..63 within stripe
    const int rg  = t >> 6;        // row group 0..3, owns rows rg*4..rg*4+3

    unsigned long long acc2[2];
    acc2[0] = 0ull; acc2[1] = 0ull;

    #pragma unroll 8
    for (int k = 0; k < Cq; k++) {
        float wv = ws[k*COLH + col];
        unsigned long long wp = pack2(wv, wv);
        float4 xv = *(const float4*)&xs[k][rg*4];
        fma2(acc2[0], pack2(xv.x, xv.y), wp);
        fma2(acc2[1], pack2(xv.z, xv.w), wp);
    }

    const int lane = t & 31;
    const int h = (colbase >> 5) + ((t >> 5) & 1);   // warp = one head
    const float a1 = a[lane], a2 = a[Fq + lane];
    #pragma unroll
    for (int p = 0; p < 2; p++) {
        float g0, g1;
        unpack2(g0, g1, acc2[p]);
        #pragma unroll
        for (int e = 0; e < 2; e++) {
            const int r = rg*4 + p*2 + e;
            const float gv = e ? g1 : g0;
            g_buf[(row0 + r)*HF + colbase + col] = gv;
            float p1 = gv*a1, p2 = gv*a2;
            #pragma unroll
            for (int o = 16; o; o >>= 1) {
                p1 += __shfl_xor_sync(0xffffffffu, p1, o);
                p2 += __shfl_xor_sync(0xffffffffu, p2, o);
            }
            if (lane == 0) {
                si_t[(i0 + r)*32 + h*8 + b] = p1;
                sj_t[(i0 + r)*32 + h*8 + b] = p2;
            }
        }
    }
}

// ---------------------------------------------------------------------------
// Aggregate (R5/R8-proven, at L2-BW floor for this structure).
__global__ void __launch_bounds__(128) gat_aggregate_kernel(float* __restrict__ out)
{
    const int i = blockIdx.x;
    const int t = threadIdx.x, w = t >> 5, lane = t & 31;

    __shared__ __align__(16) float swp[MAXN][32];   // [s][h*8+b]
    __shared__ __align__(16) int   jsafe[MAXN];
    __shared__ __align__(16) float dpart[4][32];

    const int nnz = nnz_buf[i];
    const int P   = (nnz + 3) & ~3;

    // -------- Phase 1 --------
    const float si_v = si_t[i*32 + lane];
    float wsum = 0.f;
    for (int s = w; s < P; s += 4) {
        const bool vld = s < nnz;
        int joff = vld ? jlist_buf[i*MAXN + s] : 0;   // j*512
        float sjv = sj_t[(joff >> 4) + lane];         // j*32 + lane
        float e = si_v + sjv;
        e = (e < 0.f) ? 0.2f*e : e;
        float wt = vld ? __expf(e) : 0.f;
        swp[s][lane] = wt;
        if (lane == 0) jsafe[s] = joff;
        wsum += wt;
    }
    dpart[w][lane] = wsum;
    __syncthreads();

    // -------- Phase 2 --------
    const int hp   = w & 1;
    const int b0   = (w >> 1) * 4;
    const int head = hp*2 + (lane >> 4);
    const int fp   = lane & 15;
    const int widx = head*8 + b0;

    const char* gbase = (const char*)g_buf + head*128 + fp*8;
    const char* gb0 = gbase + ((size_t)(b0+0) << 19);
    const char* gb1 = gbase + ((size_t)(b0+1) << 19);
    const char* gb2 = gbase + ((size_t)(b0+2) << 19);
    const char* gb3 = gbase + ((size_t)(b0+3) << 19);

    float2 ac0 = {0.f,0.f}, ac1 = {0.f,0.f}, ac2 = {0.f,0.f}, ac3 = {0.f,0.f};

    for (int s = 0; s < P; s += 2) {
        int2   jj = *(const int2*)&jsafe[s];
        float4 wa = *(const float4*)&swp[s][widx];
        float4 wb = *(const float4*)&swp[s+1][widx];

        float2 g00 = *(const float2*)(gb0 + jj.x);
        float2 g01 = *(const float2*)(gb1 + jj.x);
        float2 g02 = *(const float2*)(gb2 + jj.x);
        float2 g03 = *(const float2*)(gb3 + jj.x);
        float2 g10 = *(const float2*)(gb0 + jj.y);
        float2 g11 = *(const float2*)(gb1 + jj.y);
        float2 g12 = *(const float2*)(gb2 + jj.y);
        float2 g13 = *(const float2*)(gb3 + jj.y);

        ac0.x = fmaf(wa.x, g00.x, ac0.x); ac0.y = fmaf(wa.x, g00.y, ac0.y);
        ac1.x = fmaf(wa.y, g01.x, ac1.x); ac1.y = fmaf(wa.y, g01.y, ac1.y);
        ac2.x = fmaf(wa.z, g02.x, ac2.x); ac2.y = fmaf(wa.z, g02.y, ac2.y);
        ac3.x = fmaf(wa.w, g03.x, ac3.x); ac3.y = fmaf(wa.w, g03.y, ac3.y);
        ac0.x = fmaf(wb.x, g10.x, ac0.x); ac0.y = fmaf(wb.x, g10.y, ac0.y);
        ac1.x = fmaf(wb.y, g11.x, ac1.x); ac1.y = fmaf(wb.y, g11.y, ac1.y);
        ac2.x = fmaf(wb.z, g12.x, ac2.x); ac2.y = fmaf(wb.z, g12.y, ac2.y);
        ac3.x = fmaf(wb.w, g13.x, ac3.x); ac3.y = fmaf(wb.w, g13.y, ac3.y);
    }

    float4 d0 = *(const float4*)&dpart[0][widx];
    float4 d1 = *(const float4*)&dpart[1][widx];
    float4 d2 = *(const float4*)&dpart[2][widx];
    float4 d3 = *(const float4*)&dpart[3][widx];
    float dnx = (d0.x + d1.x) + (d2.x + d3.x);
    float dny = (d0.y + d1.y) + (d2.y + d3.y);
    float dnz = (d0.z + d1.z) + (d2.z + d3.z);
    float dnw = (d0.w + d1.w) + (d2.w + d3.w);

    const size_t obase = (size_t)i*HF + head*Fq + fp*2;
    float2 r0 = make_float2(__fdividef(ac0.x, dnx), __fdividef(ac0.y, dnx));
    float2 r1 = make_float2(__fdividef(ac1.x, dny), __fdividef(ac1.y, dny));
    float2 r2 = make_float2(__fdividef(ac2.x, dnz), __fdividef(ac2.y, dnz));
    float2 r3 = make_float2(__fdividef(ac3.x, dnw), __fdividef(ac3.y, dnw));
    *(float2*)&out[obase + ((size_t)(b0+0) << 17)] = r0;
    *(float2*)&out[obase + ((size_t)(b0+1) << 17)] = r1;
    *(float2*)&out[obase + ((size_t)(b0+2) << 17)] = r2;
    *(float2*)&out[obase + ((size_t)(b0+3) << 17)] = r3;
}

extern "C" void kernel_launch(void* const* d_in, const int* in_sizes, int n_in,
                              void* d_out, int out_size)
{
    const float* x   = (const float*)d_in[0];   // (B,N,C)
    const float* W   = (const float*)d_in[1];   // (C,H*F)
    const float* a   = (const float*)d_in[2];   // (2F,)
    const int*   adj = (const int*)d_in[3];     // (N,N)
    float* out = (float*)d_out;                 // (B,N,H*F)

    gat_prep_kernel<<<GEMM_BLKS + Nq, 256>>>(x, W, a, adj);
    gat_aggregate_kernel<<<Nq, 128>>>(out);
}

// round 11
// speedup vs baseline: 1.1652x; 1.1652x over previous
#include <cuda_runtime.h>
#include <cuda_fp16.h>
#include <cstdint>

#define Bq 8
#define Nq 1024
#define Cq 128
#define Hq 4
#define Fq 32
#define HF (Hq*Fq)
#define MAXN 128

// scratch (device globals; no allocation allowed)
__device__ __half g_half[Bq*Nq*HF];    // g[b][j][h][f] in fp16 (row = 256B)
__device__ float  si_t[Nq*32];         // [i][h*8+b]
__device__ float  sj_t[Nq*32];         // [j][h*8+b]
__device__ int    jlist_buf[Nq*MAXN];  // byte offsets j*256 (fp16 row stride)
__device__ int    nnz_buf[Nq];

// ---------------------------------------------------------------------------
// Kernel 0: CSR build (one block per row, 256 threads, thread owns 4 cols).
__global__ void __launch_bounds__(256) gat_csr_kernel(const int* __restrict__ adj)
{
    const int i = blockIdx.x;
    const int t = threadIdx.x, w = t >> 5, lane = t & 31;
    __shared__ int wtot[8];

    int4 v = ((const int4*)(adj + i*Nq))[t];      // cols 4t..4t+3
    unsigned m4 = 0;
    m4 |= (v.x != 0) ? 1u : 0u;  m4 |= (v.y != 0) ? 2u : 0u;
    m4 |= (v.z != 0) ? 4u : 0u;  m4 |= (v.w != 0) ? 8u : 0u;
    int cnt = __popc(m4);

    int incl = cnt;
    #pragma unroll
    for (int o = 1; o < 32; o <<= 1) {
        int n = __shfl_up_sync(0xffffffffu, incl, o);
        if (lane >= o) incl += n;
    }
    if (lane == 31) wtot[w] = incl;
    __syncthreads();
    int add = 0;
    #pragma unroll
    for (int ww = 0; ww < 8; ww++) add += (ww < w) ? wtot[ww] : 0;
    int pos = add + incl - cnt;

    unsigned mm = m4;
    while (mm) {
        int bit = __ffs(mm) - 1;
        mm &= mm - 1u;
        if (pos < MAXN) jlist_buf[i*MAXN + pos] = (t*4 + bit) * (HF*2);  // j*256
        pos++;
    }
    if (t == 255) nnz_buf[i] = min(add + incl, MAXN);
}

// ---------------------------------------------------------------------------
// Kernel 1 (R4-proven structure): g = x @ W, 8 rows/block, 128 threads, plain
// FMA; epilogue computes s_i/s_j dots and writes transposed si_t/sj_t + fp16 g.
__global__ void __launch_bounds__(128) gat_gemm_kernel(
    const float* __restrict__ x, const float* __restrict__ W,
    const float* __restrict__ a)
{
    const int t = threadIdx.x, h = t >> 5, lane = t & 31;
    const int row0 = blockIdx.x * 8;          // b*Nq + i0
    const int b    = row0 >> 10;
    const int i0   = row0 & (Nq - 1);

    __shared__ __align__(16) float xs[8][Cq];
    #pragma unroll
    for (int r = 0; r < 8; r++) xs[r][t] = x[(row0 + r)*Cq + t];
    __syncthreads();

    float acc[8];
    #pragma unroll
    for (int r = 0; r < 8; r++) acc[r] = 0.f;

    #pragma unroll 2
    for (int k = 0; k < Cq; k += 4) {
        float w0 = W[(k+0)*HF + t];
        float w1 = W[(k+1)*HF + t];
        float w2 = W[(k+2)*HF + t];
        float w3 = W[(k+3)*HF + t];
        #pragma unroll
        for (int r = 0; r < 8; r++) {
            float4 xv = *(const float4*)&xs[r][k];
            acc[r] = fmaf(xv.x, w0, acc[r]);
            acc[r] = fmaf(xv.y, w1, acc[r]);
            acc[r] = fmaf(xv.z, w2, acc[r]);
            acc[r] = fmaf(xv.w, w3, acc[r]);
        }
    }

    const float a1 = a[lane], a2 = a[Fq + lane];
    #pragma unroll
    for (int r = 0; r < 8; r++) {
        const int row = row0 + r;
        g_half[row*HF + t] = __float2half(acc[r]);
        float p1 = acc[r]*a1, p2 = acc[r]*a2;
        #pragma unroll
        for (int o = 16; o; o >>= 1) {
            p1 += __shfl_xor_sync(0xffffffffu, p1, o);
            p2 += __shfl_xor_sync(0xffffffffu, p2, o);
        }
        if (lane == 0) {
            si_t[(i0 + r)*32 + h*8 + b] = p1;   // [i][h*8+b]
            sj_t[(i0 + r)*32 + h*8 + b] = p2;
        }
    }
}

// ---------------------------------------------------------------------------
// Aggregate: block = node i, 128 threads. Phase 1: thread t = neighbor slot t,
// one coalesced 128B s_j load gives all 32 (h,b); weights -> smem (fp32).
// Phase 2: warp = head-pair x 4 batches; lane reads one __half2 (2 features)
// per (edge,batch) -> warp covers a full 128B half-row, fp32 accumulate.
// No max shift: e = lrelu(s_i+s_j) bounded, exp safe in fp32.
__global__ void __launch_bounds__(128) gat_aggregate_kernel(float* __restrict__ out)
{
    const int i = blockIdx.x;
    const int t = threadIdx.x, w = t >> 5, lane = t & 31;

    __shared__ __align__(16) float swp[MAXN][32];   // [s][h*8+b]
    __shared__ __align__(16) int   jsafe[MAXN];
    __shared__ __align__(16) float dpart[4][32];

    const int nnz = nnz_buf[i];
    const int P   = (nnz + 3) & ~3;

    // -------- Phase 1 --------
    const float si_v = si_t[i*32 + lane];
    float wsum = 0.f;
    for (int s = w; s < P; s += 4) {
        const bool vld = s < nnz;
        int joff = vld ? jlist_buf[i*MAXN + s] : 0;   // j*256
        float sjv = sj_t[(joff >> 3) + lane];         // j*32 + lane
        float e = si_v + sjv;
        e = (e < 0.f) ? 0.2f*e : e;
        float wt = vld ? __expf(e) : 0.f;
        swp[s][lane] = wt;
        if (lane == 0) jsafe[s] = joff;
        wsum += wt;
    }
    dpart[w][lane] = wsum;
    __syncthreads();

    // -------- Phase 2 --------
    const int hp   = w & 1;                 // head pair: heads {0,1} or {2,3}
    const int b0   = (w >> 1) * 4;          // batch base
    const int head = hp*2 + (lane >> 4);
    const int fp   = lane & 15;             // feature-pair index (2 feats each)
    const int widx = head*8 + b0;

    // fp16 g row = 256B; batch plane = Nq*HF*2 = 1<<18 bytes
    const char* gbase = (const char*)g_half + head*64 + fp*4;
    const char* gb0 = gbase + ((size_t)(b0+0) << 18);
    const char* gb1 = gbase + ((size_t)(b0+1) << 18);
    const char* gb2 = gbase + ((size_t)(b0+2) << 18);
    const char* gb3 = gbase + ((size_t)(b0+3) << 18);

    float2 ac0 = {0.f,0.f}, ac1 = {0.f,0.f}, ac2 = {0.f,0.f}, ac3 = {0.f,0.f};

    for (int s = 0; s < P; s += 2) {
        int2   jj = *(const int2*)&jsafe[s];
        float4 wa = *(const float4*)&swp[s][widx];
        float4 wb = *(const float4*)&swp[s+1][widx];

        float2 g00 = __half22float2(*(const __half2*)(gb0 + jj.x));
        float2 g01 = __half22float2(*(const __half2*)(gb1 + jj.x));
        float2 g02 = __half22float2(*(const __half2*)(gb2 + jj.x));
        float2 g03 = __half22float2(*(const __half2*)(gb3 + jj.x));
        float2 g10 = __half22float2(*(const __half2*)(gb0 + jj.y));
        float2 g11 = __half22float2(*(const __half2*)(gb1 + jj.y));
        float2 g12 = __half22float2(*(const __half2*)(gb2 + jj.y));
        float2 g13 = __half22float2(*(const __half2*)(gb3 + jj.y));

        ac0.x = fmaf(wa.x, g00.x, ac0.x); ac0.y = fmaf(wa.x, g00.y, ac0.y);
        ac1.x = fmaf(wa.y, g01.x, ac1.x); ac1.y = fmaf(wa.y, g01.y, ac1.y);
        ac2.x = fmaf(wa.z, g02.x, ac2.x); ac2.y = fmaf(wa.z, g02.y, ac2.y);
        ac3.x = fmaf(wa.w, g03.x, ac3.x); ac3.y = fmaf(wa.w, g03.y, ac3.y);
        ac0.x = fmaf(wb.x, g10.x, ac0.x); ac0.y = fmaf(wb.x, g10.y, ac0.y);
        ac1.x = fmaf(wb.y, g11.x, ac1.x); ac1.y = fmaf(wb.y, g11.y, ac1.y);
        ac2.x = fmaf(wb.z, g12.x, ac2.x); ac2.y = fmaf(wb.z, g12.y, ac2.y);
        ac3.x = fmaf(wb.w, g13.x, ac3.x); ac3.y = fmaf(wb.w, g13.y, ac3.y);
    }

    float4 d0 = *(const float4*)&dpart[0][widx];
    float4 d1 = *(const float4*)&dpart[1][widx];
    float4 d2 = *(const float4*)&dpart[2][widx];
    float4 d3 = *(const float4*)&dpart[3][widx];
    float dnx = (d0.x + d1.x) + (d2.x + d3.x);
    float dny = (d0.y + d1.y) + (d2.y + d3.y);
    float dnz = (d0.z + d1.z) + (d2.z + d3.z);
    float dnw = (d0.w + d1.w) + (d2.w + d3.w);

    const size_t obase = (size_t)i*HF + head*Fq + fp*2;
    float2 r0 = make_float2(__fdividef(ac0.x, dnx), __fdividef(ac0.y, dnx));
    float2 r1 = make_float2(__fdividef(ac1.x, dny), __fdividef(ac1.y, dny));
    float2 r2 = make_float2(__fdividef(ac2.x, dnz), __fdividef(ac2.y, dnz));
    float2 r3 = make_float2(__fdividef(ac3.x, dnw), __fdividef(ac3.y, dnw));
    *(float2*)&out[obase + ((size_t)(b0+0) << 17)] = r0;
    *(float2*)&out[obase + ((size_t)(b0+1) << 17)] = r1;
    *(float2*)&out[obase + ((size_t)(b0+2) << 17)] = r2;
    *(float2*)&out[obase + ((size_t)(b0+3) << 17)] = r3;
}

extern "C" void kernel_launch(void* const* d_in, const int* in_sizes, int n_in,
                              void* d_out, int out_size)
{
    const float* x   = (const float*)d_in[0];   // (B,N,C)
    const float* W   = (const float*)d_in[1];   // (C,H*F)
    const float* a   = (const float*)d_in[2];   // (2F,)
    const int*   adj = (const int*)d_in[3];     // (N,N)
    float* out = (float*)d_out;                 // (B,N,H*F)

    gat_csr_kernel<<<Nq, 256>>>(adj);
    gat_gemm_kernel<<<Bq*Nq/8, 128>>>(x, W, a);
    gat_aggregate_kernel<<<Nq, 128>>>(out);
}

// round 12
// speedup vs baseline: 1.1926x; 1.0236x over previous
#include <cuda_runtime.h>
#include <cuda_fp16.h>
#include <cstdint>

#define Bq 8
#define Nq 1024
#define Cq 128
#define Hq 4
#define Fq 32
#define HF (Hq*Fq)
#define MAXN 128

// scratch (device globals; no allocation allowed)
__device__ __half g_half[Bq*Nq*HF];    // g[b][j][h][f] in fp16 (row = 256B)
__device__ float  si_t[Nq*32];         // [i][h*8+b]
__device__ float  sj_t[Nq*32];         // [j][h*8+b]

// ---------------------------------------------------------------------------
// Kernel 1 (R4/R11-proven): g = x @ W, 8 rows/block, 128 threads, plain FMA;
// epilogue computes s_i/s_j head-dots, writes transposed si_t/sj_t + fp16 g.
__global__ void __launch_bounds__(128) gat_gemm_kernel(
    const float* __restrict__ x, const float* __restrict__ W,
    const float* __restrict__ a)
{
    const int t = threadIdx.x, h = t >> 5, lane = t & 31;
    const int row0 = blockIdx.x * 8;          // b*Nq + i0
    const int b    = row0 >> 10;
    const int i0   = row0 & (Nq - 1);

    __shared__ __align__(16) float xs[8][Cq];
    #pragma unroll
    for (int r = 0; r < 8; r++) xs[r][t] = x[(row0 + r)*Cq + t];
    __syncthreads();

    float acc[8];
    #pragma unroll
    for (int r = 0; r < 8; r++) acc[r] = 0.f;

    #pragma unroll 2
    for (int k = 0; k < Cq; k += 4) {
        float w0 = W[(k+0)*HF + t];
        float w1 = W[(k+1)*HF + t];
        float w2 = W[(k+2)*HF + t];
        float w3 = W[(k+3)*HF + t];
        #pragma unroll
        for (int r = 0; r < 8; r++) {
            float4 xv = *(const float4*)&xs[r][k];
            acc[r] = fmaf(xv.x, w0, acc[r]);
            acc[r] = fmaf(xv.y, w1, acc[r]);
            acc[r] = fmaf(xv.z, w2, acc[r]);
            acc[r] = fmaf(xv.w, w3, acc[r]);
        }
    }

    const float a1 = a[lane], a2 = a[Fq + lane];
    #pragma unroll
    for (int r = 0; r < 8; r++) {
        const int row = row0 + r;
        g_half[row*HF + t] = __float2half(acc[r]);
        float p1 = acc[r]*a1, p2 = acc[r]*a2;
        #pragma unroll
        for (int o = 16; o; o >>= 1) {
            p1 += __shfl_xor_sync(0xffffffffu, p1, o);
            p2 += __shfl_xor_sync(0xffffffffu, p2, o);
        }
        if (lane == 0) {
            si_t[(i0 + r)*32 + h*8 + b] = p1;   // [i][h*8+b]
            sj_t[(i0 + r)*32 + h*8 + b] = p2;
        }
    }
}

// ---------------------------------------------------------------------------
// Aggregate with fused CSR. Block = node i, 128 threads.
// Phase 0: compact adj row i into shared jsafe (byte offsets j*256).
// Phase 1: thread t = neighbor slot t; one coalesced 128B s_j load gives all
//          32 (h,b) weights -> smem (fp32).
// Phase 2: warp = head-pair x 4 batches; lane reads one __half2 (2 features)
//          per (edge,batch); fp32 accumulate.
// No max shift: e = lrelu(s_i+s_j) bounded, exp safe in fp32.
__global__ void __launch_bounds__(128) gat_aggregate_kernel(
    const int* __restrict__ adj, float* __restrict__ out)
{
    const int i = blockIdx.x;
    const int t = threadIdx.x, w = t >> 5, lane = t & 31;

    __shared__ __align__(16) float swp[MAXN][32];   // [s][h*8+b]
    __shared__ __align__(16) int   jsafe[MAXN];
    __shared__ __align__(16) float dpart[4][32];
    __shared__ int wtot4[4];
    __shared__ int nnz_s;

    // -------- Phase 0: CSR compaction of adj row i --------
    jsafe[t] = 0;                                    // pad slots alias j=0 (wt=0)
    const int4* arow = (const int4*)(adj + i*Nq) + t*2;
    int4 v0 = arow[0];
    int4 v1 = arow[1];
    unsigned m8 = 0;
    m8 |= (v0.x != 0) ? 0x01u : 0u;  m8 |= (v0.y != 0) ? 0x02u : 0u;
    m8 |= (v0.z != 0) ? 0x04u : 0u;  m8 |= (v0.w != 0) ? 0x08u : 0u;
    m8 |= (v1.x != 0) ? 0x10u : 0u;  m8 |= (v1.y != 0) ? 0x20u : 0u;
    m8 |= (v1.z != 0) ? 0x40u : 0u;  m8 |= (v1.w != 0) ? 0x80u : 0u;
    int cnt = __popc(m8);

    int incl = cnt;                                  // warp inclusive scan
    #pragma unroll
    for (int o = 1; o < 32; o <<= 1) {
        int n = __shfl_up_sync(0xffffffffu, incl, o);
        if (lane >= o) incl += n;
    }
    if (lane == 31) wtot4[w] = incl;
    __syncthreads();                                 // jsafe zeroed + wtot ready

    int add = 0;
    #pragma unroll
    for (int ww = 0; ww < 4; ww++) add += (ww < w) ? wtot4[ww] : 0;
    int pos = add + incl - cnt;

    unsigned mm = m8;
    while (mm) {
        int bit = __ffs(mm) - 1;
        mm &= mm - 1u;
        if (pos < MAXN) jsafe[pos] = (t*8 + bit) * (HF*2);   // j*256
        pos++;
    }
    if (t == 127) nnz_s = min(add + incl, MAXN);
    __syncthreads();

    const int nnz = nnz_s;
    const int P   = (nnz + 3) & ~3;

    // -------- Phase 1 --------
    const float si_v = si_t[i*32 + lane];
    float wsum = 0.f;
    for (int s = w; s < P; s += 4) {
        const bool vld = s < nnz;
        int joff = jsafe[s];                          // j*256 (0 if padded)
        float sjv = sj_t[(joff >> 3) + lane];         // j*32 + lane
        float e = si_v + sjv;
        e = (e < 0.f) ? 0.2f*e : e;
        float wt = vld ? __expf(e) : 0.f;
        swp[s][lane] = wt;
        wsum += wt;
    }
    dpart[w][lane] = wsum;
    __syncthreads();

    // -------- Phase 2 --------
    const int hp   = w & 1;                 // head pair: heads {0,1} or {2,3}
    const int b0   = (w >> 1) * 4;          // batch base
    const int head = hp*2 + (lane >> 4);
    const int fp   = lane & 15;             // feature-pair index (2 feats each)
    const int widx = head*8 + b0;

    // fp16 g row = 256B; batch plane = Nq*HF*2 = 1<<18 bytes
    const char* gbase = (const char*)g_half + head*64 + fp*4;
    const char* gb0 = gbase + ((size_t)(b0+0) << 18);
    const char* gb1 = gbase + ((size_t)(b0+1) << 18);
    const char* gb2 = gbase + ((size_t)(b0+2) << 18);
    const char* gb3 = gbase + ((size_t)(b0+3) << 18);

    float2 ac0 = {0.f,0.f}, ac1 = {0.f,0.f}, ac2 = {0.f,0.f}, ac3 = {0.f,0.f};

    for (int s = 0; s < P; s += 2) {
        int2   jj = *(const int2*)&jsafe[s];
        float4 wa = *(const float4*)&swp[s][widx];
        float4 wb = *(const float4*)&swp[s+1][widx];

        float2 g00 = __half22float2(*(const __half2*)(gb0 + jj.x));
        float2 g01 = __half22float2(*(const __half2*)(gb1 + jj.x));
        float2 g02 = __half22float2(*(const __half2*)(gb2 + jj.x));
        float2 g03 = __half22float2(*(const __half2*)(gb3 + jj.x));
        float2 g10 = __half22float2(*(const __half2*)(gb0 + jj.y));
        float2 g11 = __half22float2(*(const __half2*)(gb1 + jj.y));
        float2 g12 = __half22float2(*(const __half2*)(gb2 + jj.y));
        float2 g13 = __half22float2(*(const __half2*)(gb3 + jj.y));

        ac0.x = fmaf(wa.x, g00.x, ac0.x); ac0.y = fmaf(wa.x, g00.y, ac0.y);
        ac1.x = fmaf(wa.y, g01.x, ac1.x); ac1.y = fmaf(wa.y, g01.y, ac1.y);
        ac2.x = fmaf(wa.z, g02.x, ac2.x); ac2.y = fmaf(wa.z, g02.y, ac2.y);
        ac3.x = fmaf(wa.w, g03.x, ac3.x); ac3.y = fmaf(wa.w, g03.y, ac3.y);
        ac0.x = fmaf(wb.x, g10.x, ac0.x); ac0.y = fmaf(wb.x, g10.y, ac0.y);
        ac1.x = fmaf(wb.y, g11.x, ac1.x); ac1.y = fmaf(wb.y, g11.y, ac1.y);
        ac2.x = fmaf(wb.z, g12.x, ac2.x); ac2.y = fmaf(wb.z, g12.y, ac2.y);
        ac3.x = fmaf(wb.w, g13.x, ac3.x); ac3.y = fmaf(wb.w, g13.y, ac3.y);
    }

    float4 d0 = *(const float4*)&dpart[0][widx];
    float4 d1 = *(const float4*)&dpart[1][widx];
    float4 d2 = *(const float4*)&dpart[2][widx];
    float4 d3 = *(const float4*)&dpart[3][widx];
    float dnx = (d0.x + d1.x) + (d2.x + d3.x);
    float dny = (d0.y + d1.y) + (d2.y + d3.y);
    float dnz = (d0.z + d1.z) + (d2.z + d3.z);
    float dnw = (d0.w + d1.w) + (d2.w + d3.w);

    const size_t obase = (size_t)i*HF + head*Fq + fp*2;
    float2 r0 = make_float2(__fdividef(ac0.x, dnx), __fdividef(ac0.y, dnx));
    float2 r1 = make_float2(__fdividef(ac1.x, dny), __fdividef(ac1.y, dny));
    float2 r2 = make_float2(__fdividef(ac2.x, dnz), __fdividef(ac2.y, dnz));
    float2 r3 = make_float2(__fdividef(ac3.x, dnw), __fdividef(ac3.y, dnw));
    *(float2*)&out[obase + ((size_t)(b0+0) << 17)] = r0;
    *(float2*)&out[obase + ((size_t)(b0+1) << 17)] = r1;
    *(float2*)&out[obase + ((size_t)(b0+2) << 17)] = r2;
    *(float2*)&out[obase + ((size_t)(b0+3) << 17)] = r3;
}

extern "C" void kernel_launch(void* const* d_in, const int* in_sizes, int n_in,
                              void* d_out, int out_size)
{
    const float* x   = (const float*)d_in[0];   // (B,N,C)
    const float* W   = (const float*)d_in[1];   // (C,H*F)
    const float* a   = (const float*)d_in[2];   // (2F,)
    const int*   adj = (const int*)d_in[3];     // (N,N)
    float* out = (float*)d_out;                 // (B,N,H*F)

    gat_gemm_kernel<<<Bq*Nq/8, 128>>>(x, W, a);
    gat_aggregate_kernel<<<Nq, 128>>>(adj, out);
}